// round 7
// baseline (speedup 1.0000x reference)
#include <cuda_runtime.h>

#define BB 16
#define PP 16
#define CC 1024
#define DD 128
#define NBLK 296          // 2 per SM (148 SMs) -> single wave, barrier-safe
#define NITEM 1024        // (b,p) x 4 chunks of 256 candidates

__device__ float g_partial[NITEM];  // per-item exp-sum partials
__device__ int   g_arrive;          // global barrier (zero-init, self-reset)
__device__ int   g_depart;          // departures (zero-init, self-reset)

// ---------------------------------------------------------------------------
// Persistent single-wave kernel.
//  Phase 1: each block processes items blockIdx.x + k*NBLK (interleaved ->
//    clen imbalance averages out). Inner loop = R2-proven warp-dot: 4
//    independent LDG.128, butterfly reduce, lane0 exp + float4 store.
//    Per-item fixed-order partial sum -> g_partial[item].
//  Global barrier: arrive counter + spin (all NBLK blocks resident).
//  Phase 2: blocks 0..255 each normalize one (b,p) row: fixed-order sum of
//    the batch's 64 partials, then scale 256 float4 (L2-hot, written us ago).
//  Counters reset by the last departing block (all spins exited by then).
//  Row-constant score terms cancel in softmax; |score| <~ 1 so exp w/o max
//  is exact vs reference; masked entries exactly 0 (validated R2-R6).
// ---------------------------------------------------------------------------
__global__ void __launch_bounds__(256) k_persist(
    const float* __restrict__ cand_emb,
    const int*   __restrict__ cand_len,
    const float* __restrict__ score_w,
    float* __restrict__ out)
{
    __shared__ float sred[8];
    __shared__ float s_inv;

    int t = threadIdx.x, wid = t >> 5, lane = t & 31;
    float4 w4 = ((const float4*)(score_w + 3*DD))[lane];

    // ---------------- Phase 1 ----------------
    for (int item = blockIdx.x; item < NITEM; item += NBLK) {
        int bp = item >> 2, chunk = item & 3;
        int clen = cand_len[bp];
        const float4* __restrict__ ce =
            (const float4*)cand_emb + (size_t)bp * (CC*DD/4);
        float* __restrict__ orow = out + (size_t)bp * CC;

        int c0 = chunk*256 + wid*32;
        int nv = clen - c0; nv = nv < 0 ? 0 : (nv > 32 ? 32 : nv);

        float wsum = 0.f;   // meaningful on lane 0
        int j = 0;
        for (; j + 4 <= nv; j += 4) {
            int c = c0 + j;
            float4 e0 = ce[(size_t)(c+0)*32 + lane];
            float4 e1 = ce[(size_t)(c+1)*32 + lane];
            float4 e2 = ce[(size_t)(c+2)*32 + lane];
            float4 e3 = ce[(size_t)(c+3)*32 + lane];
            float s0 = e0.x*w4.x + e0.y*w4.y + e0.z*w4.z + e0.w*w4.w;
            float s1 = e1.x*w4.x + e1.y*w4.y + e1.z*w4.z + e1.w*w4.w;
            float s2 = e2.x*w4.x + e2.y*w4.y + e2.z*w4.z + e2.w*w4.w;
            float s3 = e3.x*w4.x + e3.y*w4.y + e3.z*w4.z + e3.w*w4.w;
            #pragma unroll
            for (int o = 16; o > 0; o >>= 1) {
                s0 += __shfl_xor_sync(0xffffffffu, s0, o);
                s1 += __shfl_xor_sync(0xffffffffu, s1, o);
                s2 += __shfl_xor_sync(0xffffffffu, s2, o);
                s3 += __shfl_xor_sync(0xffffffffu, s3, o);
            }
            if (lane == 0) {
                float x0 = __expf(s0), x1 = __expf(s1);
                float x2 = __expf(s2), x3 = __expf(s3);
                *(float4*)(orow + c) = make_float4(x0, x1, x2, x3);
                wsum += (x0 + x1) + (x2 + x3);
            }
        }
        for (; j < nv; j++) {
            int c = c0 + j;
            float4 e = ce[(size_t)c*32 + lane];
            float s = e.x*w4.x + e.y*w4.y + e.z*w4.z + e.w*w4.w;
            #pragma unroll
            for (int o = 16; o > 0; o >>= 1)
                s += __shfl_xor_sync(0xffffffffu, s, o);
            if (lane == 0) { float x = __expf(s); orow[c] = x; wsum += x; }
        }
        int cm = c0 + nv + lane;
        if (cm < c0 + 32) orow[cm] = 0.0f;

        if (lane == 0) sred[wid] = wsum;
        __syncthreads();
        if (t == 0) {
            float s = 0.f;
            #pragma unroll
            for (int w = 0; w < 8; w++) s += sred[w];
            g_partial[item] = s;
        }
        __syncthreads();
    }

    // ---------------- Global barrier (all NBLK resident) ----------------
    if (t == 0) {
        __threadfence();                          // release partials + exps
        atomicAdd(&g_arrive, 1);
        while (atomicAdd(&g_arrive, 0) < NBLK) __nanosleep(64);
        __threadfence();                          // acquire
    }
    __syncthreads();

    // ---------------- Phase 2: one (b,p) row per block (0..255) ----------
    if (blockIdx.x < 256) {
        int row = blockIdx.x;
        int b = row >> 4;
        if (wid == 0) {
            float v = g_partial[b*64 + lane] + g_partial[b*64 + 32 + lane];
            #pragma unroll
            for (int o = 16; o > 0; o >>= 1)
                v += __shfl_xor_sync(0xffffffffu, v, o);
            if (lane == 0) s_inv = 1.0f / v;
        }
        __syncthreads();
        float inv = s_inv;
        float4* __restrict__ row4 = (float4*)(out + (size_t)row * CC);
        float4 v = row4[t];                       // L2-hot
        v.x *= inv; v.y *= inv; v.z *= inv; v.w *= inv;
        row4[t] = v;
    }

    // ---------------- Reset for graph replay (last departer) --------------
    __syncthreads();
    if (t == 0) {
        __threadfence();
        int old = atomicAdd(&g_depart, 1);
        if (old == NBLK - 1) { g_depart = 0; g_arrive = 0; }
    }
}

// ---------------------------------------------------------------------------
extern "C" void kernel_launch(void* const* d_in, const int* in_sizes, int n_in,
                              void* d_out, int out_size)
{
    const float* cand_emb = (const float*)d_in[3];
    const int*   cand_len = (const int*)  d_in[4];
    const float* score_w  = (const float*)d_in[19];
    float* out = (float*)d_out;

    k_persist<<<NBLK, 256>>>(cand_emb, cand_len, score_w, out);
}

// round 8
// speedup vs baseline: 1.5383x; 1.5383x over previous
#include <cuda_runtime.h>

#define BB 16
#define PP 16
#define CC 1024
#define DD 128

__device__ float g_partial[BB*PP*4];  // per-block exp-sum partials (1024)
__device__ int   g_count[BB];         // arrivals per batch (zero-init, self-reset)
__device__ int   g_depart[BB];        // departures per batch (zero-init, self-reset)

// ---------------------------------------------------------------------------
// Fused kernel, grid 1024 x 256, FULLY RESIDENT (launch_bounds(256,8):
// 148 SMs x 8 blocks = 1184 >= 1024 -> per-batch spin is deadlock-free).
//
//  Phase 1 (identical to the proven R2 scores kernel): block = 256 candidates
//    of one (b,p); warp owns 32; 4 independent LDG.128 per iter, butterfly
//    reduce, lane0 exp + float4 store; masked tail zero-filled. Fixed-order
//    block partial -> g_partial[blockIdx.x].
//  Sync: arrive on g_count[b]; spin until all 64 batch blocks published.
//  Phase 2: EVERY block re-reads its own 1KB chunk (L2-hot, own writes,
//    ordered by __syncthreads) and scales by the batch inv-sum, computed by
//    each block in identical fixed order (deterministic). Zeros stay zero.
//  Reset: departure counter; last departer resets both counters (all spins
//    have provably exited by then) -> graph-replay safe.
//
//  Row-constant score terms cancel in softmax; |score| <~ 1 so exp without
//  max-subtraction matches the reference exactly (validated R2-R7, ~1.3e-7).
// ---------------------------------------------------------------------------
__global__ void __launch_bounds__(256, 8) k_fused(
    const float* __restrict__ cand_emb,
    const int*   __restrict__ cand_len,
    const float* __restrict__ score_w,
    float* __restrict__ out)
{
    __shared__ float sred[8];
    __shared__ float s_inv;

    int blk = blockIdx.x;
    int bp = blk >> 2, chunk = blk & 3, b = blk >> 6;
    int t = threadIdx.x, wid = t >> 5, lane = t & 31;

    float4 w4 = ((const float4*)(score_w + 3*DD))[lane];
    int clen = cand_len[bp];
    const float4* __restrict__ ce =
        (const float4*)cand_emb + (size_t)bp * (CC*DD/4);
    float* __restrict__ orow = out + (size_t)bp * CC;

    int c0 = chunk*256 + wid*32;
    int nv = clen - c0; nv = nv < 0 ? 0 : (nv > 32 ? 32 : nv);

    float wsum = 0.f;   // meaningful on lane 0
    int j = 0;
    for (; j + 4 <= nv; j += 4) {
        int c = c0 + j;
        float4 e0 = ce[(size_t)(c+0)*32 + lane];
        float4 e1 = ce[(size_t)(c+1)*32 + lane];
        float4 e2 = ce[(size_t)(c+2)*32 + lane];
        float4 e3 = ce[(size_t)(c+3)*32 + lane];
        float s0 = e0.x*w4.x + e0.y*w4.y + e0.z*w4.z + e0.w*w4.w;
        float s1 = e1.x*w4.x + e1.y*w4.y + e1.z*w4.z + e1.w*w4.w;
        float s2 = e2.x*w4.x + e2.y*w4.y + e2.z*w4.z + e2.w*w4.w;
        float s3 = e3.x*w4.x + e3.y*w4.y + e3.z*w4.z + e3.w*w4.w;
        #pragma unroll
        for (int o = 16; o > 0; o >>= 1) {
            s0 += __shfl_xor_sync(0xffffffffu, s0, o);
            s1 += __shfl_xor_sync(0xffffffffu, s1, o);
            s2 += __shfl_xor_sync(0xffffffffu, s2, o);
            s3 += __shfl_xor_sync(0xffffffffu, s3, o);
        }
        if (lane == 0) {
            float x0 = __expf(s0), x1 = __expf(s1);
            float x2 = __expf(s2), x3 = __expf(s3);
            *(float4*)(orow + c) = make_float4(x0, x1, x2, x3);
            wsum += (x0 + x1) + (x2 + x3);
        }
    }
    for (; j < nv; j++) {
        int c = c0 + j;
        float4 e = ce[(size_t)c*32 + lane];
        float s = e.x*w4.x + e.y*w4.y + e.z*w4.z + e.w*w4.w;
        #pragma unroll
        for (int o = 16; o > 0; o >>= 1) s += __shfl_xor_sync(0xffffffffu, s, o);
        if (lane == 0) { float x = __expf(s); orow[c] = x; wsum += x; }
    }
    int cm = c0 + nv + lane;
    if (cm < c0 + 32) orow[cm] = 0.0f;

    // ---- fixed-order block partial, publish, per-batch spin barrier ----
    if (lane == 0) sred[wid] = wsum;
    __syncthreads();
    if (t == 0) {
        float s = 0.f;
        #pragma unroll
        for (int w = 0; w < 8; w++) s += sred[w];
        g_partial[blk] = s;
        __threadfence();                          // release exps + partial
        atomicAdd(&g_count[b], 1);
        while (atomicAdd(&g_count[b], 0) < 64) __nanosleep(32);
        __threadfence();                          // acquire peers' partials
    }
    __syncthreads();

    // ---- every block: identical fixed-order batch sum -> deterministic ----
    if (wid == 0) {
        float v = g_partial[b*64 + lane] + g_partial[b*64 + 32 + lane];
        #pragma unroll
        for (int o = 16; o > 0; o >>= 1)
            v += __shfl_xor_sync(0xffffffffu, v, o);
        if (lane == 0) s_inv = 1.0f / v;
    }
    __syncthreads();
    float inv = s_inv;

    // ---- scale own 1KB chunk (L2-hot; own writes visible after syncthreads;
    //      masked zeros stay exactly zero) ----
    float* __restrict__ ochunk = orow + chunk*256;
    ochunk[t] *= inv;

    // ---- reset counters for graph replay (after all batch spins exited) ----
    __syncthreads();
    if (t == 0) {
        int old = atomicAdd(&g_depart[b], 1);
        if (old == 63) { g_depart[b] = 0; g_count[b] = 0; }
    }
}

// ---------------------------------------------------------------------------
extern "C" void kernel_launch(void* const* d_in, const int* in_sizes, int n_in,
                              void* d_out, int out_size)
{
    const float* cand_emb = (const float*)d_in[3];
    const int*   cand_len = (const int*)  d_in[4];
    const float* score_w  = (const float*)d_in[19];
    float* out = (float*)d_out;

    k_fused<<<BB*PP*4, 256>>>(cand_emb, cand_len, score_w, out);
}